// round 15
// baseline (speedup 1.0000x reference)
#include <cuda_runtime.h>
#include <cuda_bf16.h>
#include <cstdint>
#include <cmath>

// Problem constants
#define E_ 8
#define D_ 1024
#define H_ 4096
#define N_ 8192

#define NTH1 256        // g1: 8 warps, warp tile 64x32 per matrix
#define NTH2 128        // g2: 4 warps, warp tile 64x64
#define BK  64
#define G2ST 3

// Tiled-swizzled operand storage: tile = 128 rows x 64 cols bf16 = 16384 B,
// element (r, c) at byte  r*128 + (((c>>3) ^ (r&7))<<4) + (c&7)*2
#define TILB 16384
#define ST1B (6 * TILB)              // g1 stage: 2 k-tiles x (A+B1+B3) = 98304 B
#define ST2B (2 * TILB)              // g2 stage: A + B = 32768 B

__device__ __nv_bfloat16 g_xb  [(size_t)N_ * D_];
__device__ __nv_bfloat16 g_w1b [(size_t)E_ * H_ * D_];
__device__ __nv_bfloat16 g_w3b [(size_t)E_ * H_ * D_];
__device__ __nv_bfloat16 g_w2b [(size_t)E_ * D_ * H_];
__device__ __nv_bfloat16 g_hbuf[(size_t)N_ * H_];

// ---------------------------------------------------------------------------
// helpers
// ---------------------------------------------------------------------------
__device__ __forceinline__ uint32_t smem_u32(const void* p) {
    return (uint32_t)__cvta_generic_to_shared(p);
}
__device__ __forceinline__ void bulk_ld(uint32_t sdst, const void* gsrc,
                                        uint32_t bytes, uint32_t mbar) {
    asm volatile(
        "cp.async.bulk.shared::cta.global.mbarrier::complete_tx::bytes "
        "[%0], [%1], %2, [%3];\n"
        :: "r"(sdst), "l"(gsrc), "r"(bytes), "r"(mbar) : "memory");
}
#define MBAR_INIT(mb, cnt) \
    asm volatile("mbarrier.init.shared.b64 [%0], %1;" :: "r"(mb), "r"((uint32_t)(cnt)) : "memory")
#define MBAR_EXPECT(mb, bytes) \
    asm volatile("mbarrier.arrive.expect_tx.shared.b64 _, [%0], %1;" \
                 :: "r"(mb), "r"((uint32_t)(bytes)) : "memory")
#define MBAR_ARRIVE(mb) \
    asm volatile("mbarrier.arrive.shared.b64 _, [%0];" :: "r"(mb) : "memory")
#define FENCE_ASYNC() \
    asm volatile("fence.proxy.async.shared::cta;" ::: "memory")

#define MBAR_WAIT(mb, parity) do {                                             \
    uint32_t _m = (mb); uint32_t _p = (parity); uint32_t _done;                \
    asm volatile("{\n\t.reg .pred p;\n\t"                                      \
        "mbarrier.try_wait.parity.acquire.cta.shared::cta.b64 p, [%1], %2;\n\t"\
        "selp.b32 %0, 1, 0, p;\n\t}"                                           \
        : "=r"(_done) : "r"(_m), "r"(_p) : "memory");                          \
    if (!_done) {                                                              \
        asm volatile("{\n\t.reg .pred P1;\n\t"                                 \
            "WAIT_LOOP_%=:\n\t"                                                \
            "mbarrier.try_wait.parity.acquire.cta.shared::cta.b64 P1, [%0], %1, 0x989680;\n\t" \
            "@P1 bra.uni WAIT_DONE_%=;\n\t"                                    \
            "bra.uni WAIT_LOOP_%=;\n\t"                                        \
            "WAIT_DONE_%=:\n\t}"                                               \
            :: "r"(_m), "r"(_p) : "memory");                                   \
    }                                                                          \
} while (0)

__device__ __forceinline__ void ldsm_x4(uint32_t* r, uint32_t addr) {
    asm volatile("ldmatrix.sync.aligned.m8n8.x4.shared.b16 {%0,%1,%2,%3}, [%4];\n"
                 : "=r"(r[0]), "=r"(r[1]), "=r"(r[2]), "=r"(r[3]) : "r"(addr));
}
__device__ __forceinline__ void mma_bf16(float* c, const uint32_t* a, const uint32_t* b) {
    asm volatile("mma.sync.aligned.m16n8k16.row.col.f32.bf16.bf16.f32 "
                 "{%0,%1,%2,%3}, {%4,%5,%6,%7}, {%8,%9}, {%0,%1,%2,%3};\n"
                 : "+f"(c[0]), "+f"(c[1]), "+f"(c[2]), "+f"(c[3])
                 : "r"(a[0]), "r"(a[1]), "r"(a[2]), "r"(a[3]),
                   "r"(b[0]), "r"(b[1]));
}
__device__ __forceinline__ float bfr(float x) {
    return __bfloat162float(__float2bfloat16(x));
}
__device__ __forceinline__ uint32_t pack_bf16(float a, float b) {
    __nv_bfloat162 v = __float22bfloat162_rn(make_float2(a, b));
    return *reinterpret_cast<uint32_t*>(&v);
}
__device__ __forceinline__ float gelu_bf16_chain(float x) {
    float x2  = bfr(x * x);
    float x3  = bfr(x2 * x);
    float t   = bfr(bfr(0.044715f) * x3);
    float s   = bfr(x + t);
    float a   = bfr(bfr(0.7978845608028654f) * s);
    float th  = bfr(tanhf(a));
    float op  = bfr(1.0f + th);
    float cdf = bfr(0.5f * op);
    return bfr(x * cdf);
}
__device__ __forceinline__ int expert_of(const int* counts, int row0) {
    int off = 0, e = 0;
#pragma unroll
    for (int i = 0; i < E_; i++) {
        if (row0 >= off) e = i;
        off += counts[i];
    }
    return e;
}
__device__ __forceinline__ uint32_t sw_addr(uint32_t tile_base, int r, int ch) {
    return tile_base + (uint32_t)(r * 128) + ((uint32_t)(ch ^ (r & 7)) << 4);
}

// ---------------------------------------------------------------------------
// Convert + tile + swizzle: fp32 -> bf16 tiled layout.
// ---------------------------------------------------------------------------
#define XCH ((size_t)N_ * D_ / 8)
#define WCH ((size_t)E_ * H_ * D_ / 8)

__device__ __forceinline__ void cvt_chunk(const float* __restrict__ src,
                                          __nv_bfloat16* dst, int K, size_t cc) {
    const int cpr = K >> 3;
    size_t row = cc / cpr;
    int chcol  = (int)(cc - row * cpr);
    int ktile  = chcol >> 3;
    int ch     = chcol & 7;
    size_t rowTile = row >> 7;
    int r = (int)(row & 127);

    size_t tile = rowTile * (size_t)(K >> 6) + ktile;
    const float4* s4 = reinterpret_cast<const float4*>(src + row * K + (size_t)chcol * 8);
    float4 a = s4[0], b = s4[1];
    uint4 o;
    o.x = pack_bf16(a.x, a.y);
    o.y = pack_bf16(a.z, a.w);
    o.z = pack_bf16(b.x, b.y);
    o.w = pack_bf16(b.z, b.w);
    char* dp = reinterpret_cast<char*>(dst) + tile * TILB + (size_t)r * 128
             + ((size_t)(ch ^ (r & 7)) << 4);
    *reinterpret_cast<uint4*>(dp) = o;
}

#define TOTA (XCH + 2 * WCH)
__global__ __launch_bounds__(256)
void cvt_a(const float* __restrict__ x, const float* __restrict__ w1,
           const float* __restrict__ w3)
{
    size_t g = (size_t)blockIdx.x * 256 + threadIdx.x;
    if (g >= TOTA) return;
    if (g < XCH)            cvt_chunk(x,  g_xb,  D_, g);
    else if (g < XCH + WCH) cvt_chunk(w1, g_w1b, D_, g - XCH);
    else                    cvt_chunk(w3, g_w3b, D_, g - XCH - WCH);
}

// ---------------------------------------------------------------------------
// GEMM 1 (fused): g = x@w1^T, u = x@w3^T, h = gelu(g)*u -> g_hbuf (tiled bf16)
// CTA 128x128, 256 threads, warps 2(m)x4(n), warp tile 64x32 PER MATRIX
// (A fragments shared across w1/w3 + 4 n-MMAs -> 128 B/MMA crossbar load).
// Pipeline: 2 stages x 2 k-tiles (98KB/stage), rotating producer.
// grid = (33, 64): bx<32 GEMM; bx==32 w2-convert CTAs (concurrent).
// ---------------------------------------------------------------------------
__global__ __launch_bounds__(NTH1, 1)
void moe_g1(const int* __restrict__ counts, const float* __restrict__ w2)
{
    extern __shared__ char sm[];
    __shared__ __align__(8) uint64_t s_full[2];
    __shared__ __align__(8) uint64_t s_empty[2];
    __shared__ int s_e;

    const int tid  = threadIdx.x;
    const int lane = tid & 31;
    const int wid  = tid >> 5;
    const int wm   = wid >> 2;     // 0..1
    const int wn   = wid & 3;      // 0..3
    const int bx   = blockIdx.x;
    const int by   = blockIdx.y;

    // ---- convert CTAs: 64 x 256 threads x 256 chunks = WCH (w2 fp32->bf16)
    if (bx == 32) {
        size_t base = (size_t)by * 65536 + (size_t)tid;
#pragma unroll 4
        for (int i = 0; i < 256; i++)
            cvt_chunk(w2, g_w2b, H_, base + (size_t)i * NTH1);
        return;
    }

    if (tid == 0) {
        s_e = expert_of(counts, by * 128);
#pragma unroll
        for (int s = 0; s < 2; s++) {
            MBAR_INIT(smem_u32(&s_full[s]), 1);
            MBAR_INIT(smem_u32(&s_empty[s]), NTH1 / 32);
        }
        FENCE_ASYNC();
    }
    __syncthreads();
    const int e = s_e;

    const char* At  = reinterpret_cast<const char*>(g_xb)  + (size_t)(by * 16) * TILB;
    const char* B1t = reinterpret_cast<const char*>(g_w1b) + (size_t)((e * 32 + bx) * 16) * TILB;
    const char* B3t = reinterpret_cast<const char*>(g_w3b) + (size_t)((e * 32 + bx) * 16) * TILB;

    const uint32_t sb = smem_u32(sm);

    // stage T covers k-tiles 2T and 2T+1
    auto issue = [&](int T, int slot) {
        const uint32_t mb = smem_u32(&s_full[slot]);
        const uint32_t s0 = sb + slot * ST1B;
        MBAR_EXPECT(mb, 6 * TILB);
#pragma unroll
        for (int j = 0; j < 2; j++) {
            const int kt = 2 * T + j;
            const uint32_t d = s0 + j * 3 * TILB;
            bulk_ld(d,            At  + (size_t)kt * TILB, TILB, mb);
            bulk_ld(d + TILB,     B1t + (size_t)kt * TILB, TILB, mb);
            bulk_ld(d + 2 * TILB, B3t + (size_t)kt * TILB, TILB, mb);
        }
    };

    float cg[4][4][4] = {};
    float cu[4][4][4] = {};

    auto compute = [&](int slot) {
        const uint32_t st0 = sb + slot * ST1B;
#pragma unroll
        for (int j = 0; j < 2; j++) {
            const uint32_t aB  = st0 + j * 3 * TILB;
            const uint32_t b1B = aB + TILB;
            const uint32_t b3B = aB + 2 * TILB;
#pragma unroll
            for (int kk = 0; kk < 4; kk++) {
                uint32_t a[4][4];
#pragma unroll
                for (int mi = 0; mi < 4; mi++) {
                    int r  = wm * 64 + mi * 16 + (lane & 15);
                    int ch = kk * 2 + (lane >> 4);
                    ldsm_x4(a[mi], sw_addr(aB, r, ch));
                }
#pragma unroll
                for (int ni2 = 0; ni2 < 2; ni2++) {
                    int q  = lane >> 3;
                    int r  = wn * 32 + (ni2 * 2 + (q >> 1)) * 8 + (lane & 7);
                    int ch = kk * 2 + (q & 1);
                    uint32_t b1[4], b3[4];
                    ldsm_x4(b1, sw_addr(b1B, r, ch));
                    ldsm_x4(b3, sw_addr(b3B, r, ch));
#pragma unroll
                    for (int mi = 0; mi < 4; mi++) {
                        mma_bf16(cg[mi][ni2 * 2 + 0], a[mi], b1 + 0);
                        mma_bf16(cg[mi][ni2 * 2 + 1], a[mi], b1 + 2);
                        mma_bf16(cu[mi][ni2 * 2 + 0], a[mi], b3 + 0);
                        mma_bf16(cu[mi][ni2 * 2 + 1], a[mi], b3 + 2);
                    }
                }
            }
        }
    };

    const int NT = (D_ / BK) / 2;   // 8 stages of 2 k-tiles

    if (tid == 0) { issue(0, 0); issue(1, 1); }

    for (int t = 0; t < NT; t++) {
        const int slot = t & 1;
        MBAR_WAIT(smem_u32(&s_full[slot]), (uint32_t)((t >> 1) & 1));
        compute(slot);
        if (lane == 0) MBAR_ARRIVE(smem_u32(&s_empty[slot]));
        // rotating producer: warp t issues stage t+2 (t < 8 == warp count)
        if (wid == t && lane == 0) {
            const int T = t + 2;
            if (T < NT) {
                MBAR_WAIT(smem_u32(&s_empty[T & 1]),
                          (uint32_t)(((T >> 1) - 1) & 1));
                issue(T, T & 1);
            }
        }
    }

    // epilogue: bf16-rounded gelu(g)*u -> h in tiled-swizzled layout
    const int tr = lane >> 2;
    const int tc = (lane & 3) << 1;
#pragma unroll
    for (int mi = 0; mi < 4; mi++) {
#pragma unroll
        for (int ni = 0; ni < 4; ni++) {
#pragma unroll
            for (int rr = 0; rr < 2; rr++) {
                int rl = wm * 64 + mi * 16 + rr * 8 + tr;
                int cl = wn * 32 + ni * 8 + tc;
                float g0 = bfr(cg[mi][ni][rr * 2 + 0]);
                float g1 = bfr(cg[mi][ni][rr * 2 + 1]);
                float u0 = bfr(cu[mi][ni][rr * 2 + 0]);
                float u1 = bfr(cu[mi][ni][rr * 2 + 1]);
                uint32_t hv = pack_bf16(gelu_bf16_chain(g0) * u0,
                                        gelu_bf16_chain(g1) * u1);
                int cin  = cl & 63;
                size_t tile = (size_t)by * 64 + (size_t)(bx * 2 + (cl >> 6));
                char* dp = reinterpret_cast<char*>(g_hbuf) + tile * TILB
                         + (size_t)rl * 128
                         + ((size_t)((cin >> 3) ^ (rl & 7)) << 4) + (cin & 7) * 2;
                *reinterpret_cast<uint32_t*>(dp) = hv;
            }
        }
    }
}

// ---------------------------------------------------------------------------
// GEMM 2: out = h @ w2^T. CTA 128x128, 128 threads, warps 2(m)x2(n),
// warp tile 64x64 (128 B/MMA crossbar). 2 CTAs/SM, 3-stage bulk pipeline,
// rotating producer (warp kt%4).
// grid = (D/128, N_/128) = (8, 64)
// ---------------------------------------------------------------------------
__global__ __launch_bounds__(NTH2, 2)
void moe_g2(const int* __restrict__ counts, float* __restrict__ out)
{
    extern __shared__ char sm[];
    __shared__ __align__(8) uint64_t s_full[G2ST];
    __shared__ __align__(8) uint64_t s_empty[G2ST];
    __shared__ int s_e;

    const int tid  = threadIdx.x;
    const int lane = tid & 31;
    const int wid  = tid >> 5;     // 0..3
    const int wm   = wid >> 1;     // 0..1
    const int wn   = wid & 1;      // 0..1
    const int bx   = blockIdx.x;
    const int by   = blockIdx.y;
    const int row0 = by * 128;
    const int col0 = bx * 128;

    if (tid == 0) {
        s_e = expert_of(counts, row0);
#pragma unroll
        for (int s = 0; s < G2ST; s++) {
            MBAR_INIT(smem_u32(&s_full[s]), 1);
            MBAR_INIT(smem_u32(&s_empty[s]), NTH2 / 32);
        }
        FENCE_ASYNC();
    }
    __syncthreads();
    const int e = s_e;

    const char* At = reinterpret_cast<const char*>(g_hbuf) + (size_t)(by * 64) * TILB;
    const char* Bt = reinterpret_cast<const char*>(g_w2b)  + (size_t)((e * 8 + bx) * 64) * TILB;

    const uint32_t sb = smem_u32(sm);

    auto issue = [&](int kt, int slot) {
        const uint32_t mb = smem_u32(&s_full[slot]);
        const uint32_t s0 = sb + slot * ST2B;
        MBAR_EXPECT(mb, 2 * TILB);
        bulk_ld(s0,        At + (size_t)kt * TILB, TILB, mb);
        bulk_ld(s0 + TILB, Bt + (size_t)kt * TILB, TILB, mb);
    };

    float co[4][8][4] = {};

    auto compute = [&](int slot) {
        const uint32_t aB = sb + slot * ST2B;
        const uint32_t bB = aB + TILB;
#pragma unroll
        for (int kk = 0; kk < 4; kk++) {
            uint32_t a[4][4];
#pragma unroll
            for (int mi = 0; mi < 4; mi++) {
                int r  = wm * 64 + mi * 16 + (lane & 15);
                int ch = kk * 2 + (lane >> 4);
                ldsm_x4(a[mi], sw_addr(aB, r, ch));
            }
#pragma unroll
            for (int ni2 = 0; ni2 < 4; ni2++) {
                int q  = lane >> 3;
                int r  = wn * 64 + (ni2 * 2 + (q >> 1)) * 8 + (lane & 7);
                int ch = kk * 2 + (q & 1);
                uint32_t b[4];
                ldsm_x4(b, sw_addr(bB, r, ch));
#pragma unroll
                for (int mi = 0; mi < 4; mi++) {
                    mma_bf16(co[mi][ni2 * 2 + 0], a[mi], b + 0);
                    mma_bf16(co[mi][ni2 * 2 + 1], a[mi], b + 2);
                }
            }
        }
    };

    const int NK = H_ / BK;   // 64

    if (tid == 0) {
#pragma unroll
        for (int s = 0; s < G2ST - 1; s++) issue(s, s);
    }

    for (int kt = 0; kt < NK; kt++) {
        const int slot = kt % G2ST;
        MBAR_WAIT(smem_u32(&s_full[slot]), (uint32_t)((kt / G2ST) & 1));
        compute(slot);
        if (lane == 0) MBAR_ARRIVE(smem_u32(&s_empty[slot]));
        // rotating producer: warp (kt & 3) issues stage kt+2
        if (wid == (kt & 3) && lane == 0) {
            const int T = kt + G2ST - 1;
            if (T < NK) {
                const int ts = T % G2ST;
                if (T >= G2ST)
                    MBAR_WAIT(smem_u32(&s_empty[ts]),
                              (uint32_t)(((T / G2ST) - 1) & 1));
                issue(T, ts);
            }
        }
    }

    // epilogue: round accumulator through bf16, store fp32
    const int tr = lane >> 2;
    const int tc = (lane & 3) << 1;
#pragma unroll
    for (int mi = 0; mi < 4; mi++) {
#pragma unroll
        for (int ni = 0; ni < 8; ni++) {
#pragma unroll
            for (int rr = 0; rr < 2; rr++) {
                int r = row0 + wm * 64 + mi * 16 + rr * 8 + tr;
                int c = col0 + wn * 64 + ni * 8 + tc;
                float2 ov;
                ov.x = bfr(co[mi][ni][rr * 2 + 0]);
                ov.y = bfr(co[mi][ni][rr * 2 + 1]);
                *reinterpret_cast<float2*>(&out[(size_t)r * D_ + c]) = ov;
            }
        }
    }
}

// ---------------------------------------------------------------------------
// launch — cvt_a, g1 (GEMM + embedded w2-convert CTAs), g2
// ---------------------------------------------------------------------------
extern "C" void kernel_launch(void* const* d_in, const int* in_sizes, int n_in,
                              void* d_out, int out_size) {
    const float* x      = (const float*)d_in[0];
    const float* w1     = (const float*)d_in[1];
    const float* w2     = (const float*)d_in[2];
    const float* w3     = (const float*)d_in[3];
    const int*   counts = (const int*)d_in[4];
    float* out = (float*)d_out;

    cudaFuncSetAttribute(moe_g1, cudaFuncAttributeMaxDynamicSharedMemorySize,
                         2 * ST1B);
    cudaFuncSetAttribute(moe_g2, cudaFuncAttributeMaxDynamicSharedMemorySize,
                         G2ST * ST2B);

    {
        size_t blocksA = (TOTA + 255) / 256;
        cvt_a<<<(unsigned)blocksA, 256>>>(x, w1, w3);
    }

    dim3 g1(33, N_ / 128);         // (33, 64): 32 GEMM cols + 1 convert col
    moe_g1<<<g1, NTH1, 2 * ST1B>>>(counts, w2);

    dim3 g2(D_ / 128, N_ / 128);   // (8, 64)
    moe_g2<<<g2, NTH2, G2ST * ST2B>>>(counts, out);
}

// round 16
// speedup vs baseline: 1.0500x; 1.0500x over previous
#include <cuda_runtime.h>
#include <cuda_bf16.h>
#include <cstdint>
#include <cmath>

// Problem constants
#define E_ 8
#define D_ 1024
#define H_ 4096
#define N_ 8192

#define NTH1 512
#define NTH2 256
#define BK  64
#define G2ST 3          // g2 pipeline stages

// Tiled-swizzled operand storage: tile = 128 rows x 64 cols bf16 = 16384 B,
// element (r, c) at byte  r*128 + (((c>>3) ^ (r&7))<<4) + (c&7)*2
#define TILB 16384
#define ST1B (6 * TILB)              // g1 stage: 2 k-tiles x (A+B1+B3) = 98304 B
#define ST2B (2 * TILB)              // g2 stage: A + B = 32768 B

__device__ __nv_bfloat16 g_xb  [(size_t)N_ * D_];
__device__ __nv_bfloat16 g_w1b [(size_t)E_ * H_ * D_];
__device__ __nv_bfloat16 g_w3b [(size_t)E_ * H_ * D_];
__device__ __nv_bfloat16 g_w2b [(size_t)E_ * D_ * H_];
__device__ __nv_bfloat16 g_hbuf[(size_t)N_ * H_];

// ---------------------------------------------------------------------------
// helpers
// ---------------------------------------------------------------------------
__device__ __forceinline__ uint32_t smem_u32(const void* p) {
    return (uint32_t)__cvta_generic_to_shared(p);
}
__device__ __forceinline__ void bulk_ld(uint32_t sdst, const void* gsrc,
                                        uint32_t bytes, uint32_t mbar) {
    asm volatile(
        "cp.async.bulk.shared::cta.global.mbarrier::complete_tx::bytes "
        "[%0], [%1], %2, [%3];\n"
        :: "r"(sdst), "l"(gsrc), "r"(bytes), "r"(mbar) : "memory");
}
#define MBAR_INIT(mb, cnt) \
    asm volatile("mbarrier.init.shared.b64 [%0], %1;" :: "r"(mb), "r"((uint32_t)(cnt)) : "memory")
#define MBAR_EXPECT(mb, bytes) \
    asm volatile("mbarrier.arrive.expect_tx.shared.b64 _, [%0], %1;" \
                 :: "r"(mb), "r"((uint32_t)(bytes)) : "memory")
#define MBAR_ARRIVE(mb) \
    asm volatile("mbarrier.arrive.shared.b64 _, [%0];" :: "r"(mb) : "memory")
#define FENCE_ASYNC() \
    asm volatile("fence.proxy.async.shared::cta;" ::: "memory")

#define MBAR_WAIT(mb, parity) do {                                             \
    uint32_t _m = (mb); uint32_t _p = (parity); uint32_t _done;                \
    asm volatile("{\n\t.reg .pred p;\n\t"                                      \
        "mbarrier.try_wait.parity.acquire.cta.shared::cta.b64 p, [%1], %2;\n\t"\
        "selp.b32 %0, 1, 0, p;\n\t}"                                           \
        : "=r"(_done) : "r"(_m), "r"(_p) : "memory");                          \
    if (!_done) {                                                              \
        asm volatile("{\n\t.reg .pred P1;\n\t"                                 \
            "WAIT_LOOP_%=:\n\t"                                                \
            "mbarrier.try_wait.parity.acquire.cta.shared::cta.b64 P1, [%0], %1, 0x989680;\n\t" \
            "@P1 bra.uni WAIT_DONE_%=;\n\t"                                    \
            "bra.uni WAIT_LOOP_%=;\n\t"                                        \
            "WAIT_DONE_%=:\n\t}"                                               \
            :: "r"(_m), "r"(_p) : "memory");                                   \
    }                                                                          \
} while (0)

__device__ __forceinline__ void ldsm_x4(uint32_t* r, uint32_t addr) {
    asm volatile("ldmatrix.sync.aligned.m8n8.x4.shared.b16 {%0,%1,%2,%3}, [%4];\n"
                 : "=r"(r[0]), "=r"(r[1]), "=r"(r[2]), "=r"(r[3]) : "r"(addr));
}
__device__ __forceinline__ void mma_bf16(float* c, const uint32_t* a, const uint32_t* b) {
    asm volatile("mma.sync.aligned.m16n8k16.row.col.f32.bf16.bf16.f32 "
                 "{%0,%1,%2,%3}, {%4,%5,%6,%7}, {%8,%9}, {%0,%1,%2,%3};\n"
                 : "+f"(c[0]), "+f"(c[1]), "+f"(c[2]), "+f"(c[3])
                 : "r"(a[0]), "r"(a[1]), "r"(a[2]), "r"(a[3]),
                   "r"(b[0]), "r"(b[1]));
}
__device__ __forceinline__ float bfr(float x) {
    return __bfloat162float(__float2bfloat16(x));
}
__device__ __forceinline__ uint32_t pack_bf16(float a, float b) {
    __nv_bfloat162 v = __float22bfloat162_rn(make_float2(a, b));
    return *reinterpret_cast<uint32_t*>(&v);
}
__device__ __forceinline__ float gelu_bf16_chain(float x) {
    float x2  = bfr(x * x);
    float x3  = bfr(x2 * x);
    float t   = bfr(bfr(0.044715f) * x3);
    float s   = bfr(x + t);
    float a   = bfr(bfr(0.7978845608028654f) * s);
    float th  = bfr(tanhf(a));
    float op  = bfr(1.0f + th);
    float cdf = bfr(0.5f * op);
    return bfr(x * cdf);
}
__device__ __forceinline__ int expert_of(const int* counts, int row0) {
    int off = 0, e = 0;
#pragma unroll
    for (int i = 0; i < E_; i++) {
        if (row0 >= off) e = i;
        off += counts[i];
    }
    return e;
}
__device__ __forceinline__ uint32_t sw_addr(uint32_t tile_base, int r, int ch) {
    return tile_base + (uint32_t)(r * 128) + ((uint32_t)(ch ^ (r & 7)) << 4);
}

// ---------------------------------------------------------------------------
// Convert + tile + swizzle: fp32 -> bf16 tiled layout.
// ---------------------------------------------------------------------------
#define XCH ((size_t)N_ * D_ / 8)
#define WCH ((size_t)E_ * H_ * D_ / 8)

__device__ __forceinline__ void cvt_chunk(const float* __restrict__ src,
                                          __nv_bfloat16* dst, int K, size_t cc) {
    const int cpr = K >> 3;
    size_t row = cc / cpr;
    int chcol  = (int)(cc - row * cpr);
    int ktile  = chcol >> 3;
    int ch     = chcol & 7;
    size_t rowTile = row >> 7;
    int r = (int)(row & 127);

    size_t tile = rowTile * (size_t)(K >> 6) + ktile;
    const float4* s4 = reinterpret_cast<const float4*>(src + row * K + (size_t)chcol * 8);
    float4 a = s4[0], b = s4[1];
    uint4 o;
    o.x = pack_bf16(a.x, a.y);
    o.y = pack_bf16(a.z, a.w);
    o.z = pack_bf16(b.x, b.y);
    o.w = pack_bf16(b.z, b.w);
    char* dp = reinterpret_cast<char*>(dst) + tile * TILB + (size_t)r * 128
             + ((size_t)(ch ^ (r & 7)) << 4);
    *reinterpret_cast<uint4*>(dp) = o;
}

#define TOTA (XCH + 2 * WCH)
__global__ __launch_bounds__(256)
void cvt_a(const float* __restrict__ x, const float* __restrict__ w1,
           const float* __restrict__ w3)
{
    size_t g = (size_t)blockIdx.x * 256 + threadIdx.x;
    if (g >= TOTA) return;
    if (g < XCH)            cvt_chunk(x,  g_xb,  D_, g);
    else if (g < XCH + WCH) cvt_chunk(w1, g_w1b, D_, g - XCH);
    else                    cvt_chunk(w3, g_w3b, D_, g - XCH - WCH);
}

// ---------------------------------------------------------------------------
// GEMM 1 (fused): g = x@w1^T, u = x@w3^T, h = gelu(g)*u -> g_hbuf (tiled bf16)
// CTA 128x128, 512 threads, warps 4(m)x4(n).
// Pipeline: 2 stages x 2 k-tiles (98KB/stage), rotating producer.
// grid = (33, 64): bx<32 GEMM (PDL-sync on cvt_a output); bx==32 w2-convert
// CTAs which read ONLY harness inputs -> skip the dependency sync and run
// fully overlapped with cvt_a.
// ---------------------------------------------------------------------------
__global__ __launch_bounds__(NTH1, 1)
void moe_g1(const int* __restrict__ counts, const float* __restrict__ w2)
{
    extern __shared__ char sm[];
    __shared__ __align__(8) uint64_t s_full[2];
    __shared__ __align__(8) uint64_t s_empty[2];
    __shared__ int s_e;

    const int tid  = threadIdx.x;
    const int lane = tid & 31;
    const int wid  = tid >> 5;
    const int wm   = wid >> 2;
    const int wn   = wid & 3;
    const int bx   = blockIdx.x;
    const int by   = blockIdx.y;

    // ---- convert CTAs: inputs only -> no dependency sync needed
    if (bx == 32) {
        size_t base = (size_t)by * 65536 + (size_t)tid;
#pragma unroll 4
        for (int i = 0; i < 128; i++)
            cvt_chunk(w2, g_w2b, H_, base + (size_t)i * NTH1);
#if __CUDA_ARCH__ >= 900
        cudaTriggerProgrammaticLaunchCompletion();
#endif
        return;
    }

    if (tid == 0) {
        s_e = expert_of(counts, by * 128);
#pragma unroll
        for (int s = 0; s < 2; s++) {
            MBAR_INIT(smem_u32(&s_full[s]), 1);
            MBAR_INIT(smem_u32(&s_empty[s]), NTH1 / 32);
        }
        FENCE_ASYNC();
    }
    __syncthreads();
    const int e = s_e;

    // GEMM path consumes cvt_a output -> wait for the dependency
#if __CUDA_ARCH__ >= 900
    cudaGridDependencySynchronize();
#endif

    const char* At  = reinterpret_cast<const char*>(g_xb)  + (size_t)(by * 16) * TILB;
    const char* B1t = reinterpret_cast<const char*>(g_w1b) + (size_t)((e * 32 + bx) * 16) * TILB;
    const char* B3t = reinterpret_cast<const char*>(g_w3b) + (size_t)((e * 32 + bx) * 16) * TILB;

    const uint32_t sb = smem_u32(sm);

    // stage T covers k-tiles 2T and 2T+1
    auto issue = [&](int T, int slot) {
        const uint32_t mb = smem_u32(&s_full[slot]);
        const uint32_t s0 = sb + slot * ST1B;
        MBAR_EXPECT(mb, 6 * TILB);
#pragma unroll
        for (int j = 0; j < 2; j++) {
            const int kt = 2 * T + j;
            const uint32_t d = s0 + j * 3 * TILB;
            bulk_ld(d,            At  + (size_t)kt * TILB, TILB, mb);
            bulk_ld(d + TILB,     B1t + (size_t)kt * TILB, TILB, mb);
            bulk_ld(d + 2 * TILB, B3t + (size_t)kt * TILB, TILB, mb);
        }
    };

    float cg[2][4][4] = {};
    float cu[2][4][4] = {};

    auto compute = [&](int slot) {
        const uint32_t st0 = sb + slot * ST1B;
#pragma unroll
        for (int j = 0; j < 2; j++) {
            const uint32_t aB  = st0 + j * 3 * TILB;
            const uint32_t b1B = aB + TILB;
            const uint32_t b3B = aB + 2 * TILB;
#pragma unroll
            for (int kk = 0; kk < 4; kk++) {
                uint32_t a[2][4];
#pragma unroll
                for (int mi = 0; mi < 2; mi++) {
                    int r  = wm * 32 + mi * 16 + (lane & 15);
                    int ch = kk * 2 + (lane >> 4);
                    ldsm_x4(a[mi], sw_addr(aB, r, ch));
                }
#pragma unroll
                for (int ni2 = 0; ni2 < 2; ni2++) {
                    int q  = lane >> 3;
                    int r  = wn * 32 + (ni2 * 2 + (q >> 1)) * 8 + (lane & 7);
                    int ch = kk * 2 + (q & 1);
                    uint32_t b1[4], b3[4];
                    ldsm_x4(b1, sw_addr(b1B, r, ch));
                    ldsm_x4(b3, sw_addr(b3B, r, ch));
#pragma unroll
                    for (int mi = 0; mi < 2; mi++) {
                        mma_bf16(cg[mi][ni2 * 2 + 0], a[mi], b1 + 0);
                        mma_bf16(cg[mi][ni2 * 2 + 1], a[mi], b1 + 2);
                        mma_bf16(cu[mi][ni2 * 2 + 0], a[mi], b3 + 0);
                        mma_bf16(cu[mi][ni2 * 2 + 1], a[mi], b3 + 2);
                    }
                }
            }
        }
    };

    const int NT = (D_ / BK) / 2;   // 8 stages of 2 k-tiles

    if (tid == 0) { issue(0, 0); issue(1, 1); }

    for (int t = 0; t < NT; t++) {
        const int slot = t & 1;
        MBAR_WAIT(smem_u32(&s_full[slot]), (uint32_t)((t >> 1) & 1));
        compute(slot);
        if (lane == 0) MBAR_ARRIVE(smem_u32(&s_empty[slot]));
        // rotating producer: warp t issues stage t+2
        if (wid == t && lane == 0) {
            const int T = t + 2;
            if (T < NT) {
                MBAR_WAIT(smem_u32(&s_empty[T & 1]),
                          (uint32_t)(((T >> 1) - 1) & 1));
                issue(T, T & 1);
            }
        }
    }

    // epilogue: bf16-rounded gelu(g)*u -> h in tiled-swizzled layout
    const int tr = lane >> 2;
    const int tc = (lane & 3) << 1;
#pragma unroll
    for (int mi = 0; mi < 2; mi++) {
#pragma unroll
        for (int ni = 0; ni < 4; ni++) {
#pragma unroll
            for (int rr = 0; rr < 2; rr++) {
                int rl = wm * 32 + mi * 16 + rr * 8 + tr;
                int cl = wn * 32 + ni * 8 + tc;
                float g0 = bfr(cg[mi][ni][rr * 2 + 0]);
                float g1 = bfr(cg[mi][ni][rr * 2 + 1]);
                float u0 = bfr(cu[mi][ni][rr * 2 + 0]);
                float u1 = bfr(cu[mi][ni][rr * 2 + 1]);
                uint32_t hv = pack_bf16(gelu_bf16_chain(g0) * u0,
                                        gelu_bf16_chain(g1) * u1);
                int cin  = cl & 63;
                size_t tile = (size_t)by * 64 + (size_t)(bx * 2 + (cl >> 6));
                char* dp = reinterpret_cast<char*>(g_hbuf) + tile * TILB
                         + (size_t)rl * 128
                         + ((size_t)((cin >> 3) ^ (rl & 7)) << 4) + (cin & 7) * 2;
                *reinterpret_cast<uint32_t*>(dp) = hv;
            }
        }
    }
#if __CUDA_ARCH__ >= 900
    cudaTriggerProgrammaticLaunchCompletion();
#endif
}

// ---------------------------------------------------------------------------
// GEMM 2: out = h @ w2^T. CTA 128x128, 256 threads, warps 2(m)x4(n),
// 2 CTAs/SM, 3-stage bulk pipeline, rotating producer (warp kt%8).
// PDL: mbarrier init pre-sync; dependency sync before first TMA issue.
// grid = (D/128, N_/128) = (8, 64)
// ---------------------------------------------------------------------------
__global__ __launch_bounds__(NTH2, 2)
void moe_g2(const int* __restrict__ counts, float* __restrict__ out)
{
    extern __shared__ char sm[];
    __shared__ __align__(8) uint64_t s_full[G2ST];
    __shared__ __align__(8) uint64_t s_empty[G2ST];
    __shared__ int s_e;

    const int tid  = threadIdx.x;
    const int lane = tid & 31;
    const int wid  = tid >> 5;
    const int wm   = wid >> 2;
    const int wn   = wid & 3;
    const int bx   = blockIdx.x;
    const int by   = blockIdx.y;
    const int row0 = by * 128;
    const int col0 = bx * 128;

    if (tid == 0) {
        s_e = expert_of(counts, row0);
#pragma unroll
        for (int s = 0; s < G2ST; s++) {
            MBAR_INIT(smem_u32(&s_full[s]), 1);
            MBAR_INIT(smem_u32(&s_empty[s]), NTH2 / 32);
        }
        FENCE_ASYNC();
    }
    __syncthreads();
    const int e = s_e;

#if __CUDA_ARCH__ >= 900
    cudaGridDependencySynchronize();
#endif

    const char* At = reinterpret_cast<const char*>(g_hbuf) + (size_t)(by * 64) * TILB;
    const char* Bt = reinterpret_cast<const char*>(g_w2b)  + (size_t)((e * 8 + bx) * 64) * TILB;

    const uint32_t sb = smem_u32(sm);

    auto issue = [&](int kt, int slot) {
        const uint32_t mb = smem_u32(&s_full[slot]);
        const uint32_t s0 = sb + slot * ST2B;
        MBAR_EXPECT(mb, 2 * TILB);
        bulk_ld(s0,        At + (size_t)kt * TILB, TILB, mb);
        bulk_ld(s0 + TILB, Bt + (size_t)kt * TILB, TILB, mb);
    };

    float co[4][4][4] = {};

    auto compute = [&](int slot) {
        const uint32_t aB = sb + slot * ST2B;
        const uint32_t bB = aB + TILB;
#pragma unroll
        for (int kk = 0; kk < 4; kk++) {
            uint32_t a[4][4];
#pragma unroll
            for (int mi = 0; mi < 4; mi++) {
                int r  = wm * 64 + mi * 16 + (lane & 15);
                int ch = kk * 2 + (lane >> 4);
                ldsm_x4(a[mi], sw_addr(aB, r, ch));
            }
#pragma unroll
            for (int ni2 = 0; ni2 < 2; ni2++) {
                int q  = lane >> 3;
                int r  = wn * 32 + (ni2 * 2 + (q >> 1)) * 8 + (lane & 7);
                int ch = kk * 2 + (q & 1);
                uint32_t b[4];
                ldsm_x4(b, sw_addr(bB, r, ch));
#pragma unroll
                for (int mi = 0; mi < 4; mi++) {
                    mma_bf16(co[mi][ni2 * 2 + 0], a[mi], b + 0);
                    mma_bf16(co[mi][ni2 * 2 + 1], a[mi], b + 2);
                }
            }
        }
    };

    const int NK = H_ / BK;   // 64

    if (tid == 0) {
#pragma unroll
        for (int s = 0; s < G2ST - 1; s++) issue(s, s);
    }

    for (int kt = 0; kt < NK; kt++) {
        const int slot = kt % G2ST;
        MBAR_WAIT(smem_u32(&s_full[slot]), (uint32_t)((kt / G2ST) & 1));
        compute(slot);
        if (lane == 0) MBAR_ARRIVE(smem_u32(&s_empty[slot]));
        // rotating producer: warp (kt & 7) issues stage kt+2
        if (wid == (kt & 7) && lane == 0) {
            const int T = kt + G2ST - 1;
            if (T < NK) {
                const int ts = T % G2ST;
                if (T >= G2ST)
                    MBAR_WAIT(smem_u32(&s_empty[ts]),
                              (uint32_t)(((T / G2ST) - 1) & 1));
                issue(T, ts);
            }
        }
    }

    // epilogue: round accumulator through bf16, store fp32
    const int tr = lane >> 2;
    const int tc = (lane & 3) << 1;
#pragma unroll
    for (int mi = 0; mi < 4; mi++) {
#pragma unroll
        for (int ni = 0; ni < 4; ni++) {
#pragma unroll
            for (int rr = 0; rr < 2; rr++) {
                int r = row0 + wm * 64 + mi * 16 + rr * 8 + tr;
                int c = col0 + wn * 32 + ni * 8 + tc;
                float2 ov;
                ov.x = bfr(co[mi][ni][rr * 2 + 0]);
                ov.y = bfr(co[mi][ni][rr * 2 + 1]);
                *reinterpret_cast<float2*>(&out[(size_t)r * D_ + c]) = ov;
            }
        }
    }
}

// ---------------------------------------------------------------------------
// launch — cvt_a, then g1 and g2 with programmatic dependent launch so
// g1's convert CTAs overlap cvt_a and g2's prologue overlaps g1's tail.
// ---------------------------------------------------------------------------
extern "C" void kernel_launch(void* const* d_in, const int* in_sizes, int n_in,
                              void* d_out, int out_size) {
    const float* x      = (const float*)d_in[0];
    const float* w1     = (const float*)d_in[1];
    const float* w2     = (const float*)d_in[2];
    const float* w3     = (const float*)d_in[3];
    const int*   counts = (const int*)d_in[4];
    float* out = (float*)d_out;

    cudaFuncSetAttribute(moe_g1, cudaFuncAttributeMaxDynamicSharedMemorySize,
                         2 * ST1B);
    cudaFuncSetAttribute(moe_g2, cudaFuncAttributeMaxDynamicSharedMemorySize,
                         G2ST * ST2B);

    {
        size_t blocksA = (TOTA + 255) / 256;
        cvt_a<<<(unsigned)blocksA, 256>>>(x, w1, w3);
    }

    {
        cudaLaunchConfig_t cfg = {};
        cfg.gridDim = dim3(33, N_ / 128, 1);   // 32 GEMM cols + 1 convert col
        cfg.blockDim = dim3(NTH1, 1, 1);
        cfg.dynamicSmemBytes = 2 * ST1B;
        cfg.stream = 0;
        cudaLaunchAttribute attr[1];
        attr[0].id = cudaLaunchAttributeProgrammaticStreamSerialization;
        attr[0].val.programmaticStreamSerializationAllowed = 1;
        cfg.attrs = attr;
        cfg.numAttrs = 1;
        cudaLaunchKernelEx(&cfg, moe_g1, counts, w2);
    }

    {
        cudaLaunchConfig_t cfg = {};
        cfg.gridDim = dim3(D_ / 128, N_ / 128, 1);
        cfg.blockDim = dim3(NTH2, 1, 1);
        cfg.dynamicSmemBytes = G2ST * ST2B;
        cfg.stream = 0;
        cudaLaunchAttribute attr[1];
        attr[0].id = cudaLaunchAttributeProgrammaticStreamSerialization;
        attr[0].val.programmaticStreamSerializationAllowed = 1;
        cfg.attrs = attr;
        cfg.numAttrs = 1;
        cudaLaunchKernelEx(&cfg, moe_g2, counts, out);
    }
}